// round 4
// baseline (speedup 1.0000x reference)
#include <cuda_runtime.h>
#include <cuda_bf16.h>
#include <cstdint>

// ---------------- problem constants ----------------
#define DD 32
#define MMODES 64
#define BB 16
#define NN 1024
#define FF 2080
#define FP 2176            // FF padded to 17*128
#define NROWT 17           // f row tiles (BM=128)
#define NCOLT 33           // g col tiles (BN=64)
#define NPAIR2 289         // sum_{tf=0..16} (33-2*tf)

// ---------------- GEMM tiling ----------------
#define BM 128
#define BN 64
#define BKC 32             // K per chunk (bf16 -> 64B rows)
#define NCH 32             // NN / BKC
#define KS 2               // k16 steps per chunk
#define NSTAGE 3

// smem layout: 6 X planes (128x64B) + 6 Y planes (64x64B) per stage
#define XPL 8192
#define YPL 4096
#define YOFF 49152                 // 6 * XPL
#define STAGE_BYTES 73728          // 6*XPL + 6*YPL
#define SMEM_DYN (NSTAGE * STAGE_BYTES + 1024)   // 222208 + pad

// epilogue staging (reuses stage smem)
#define PITCH_T 136
#define PLANE_T 17408              // 128 * 136
#define PITCH_O 528

// ---------------- device scratch (bf16 split planes) ----------------
// Amp planes: r, i, s=r+i, m=r-i (hi/lo each)
__device__ __nv_bfloat16 gArh[(size_t)FP * NN];
__device__ __nv_bfloat16 gArl[(size_t)FP * NN];
__device__ __nv_bfloat16 gAih[(size_t)FP * NN];
__device__ __nv_bfloat16 gAil[(size_t)FP * NN];
__device__ __nv_bfloat16 gAsh[(size_t)FP * NN];
__device__ __nv_bfloat16 gAsl[(size_t)FP * NN];
__device__ __nv_bfloat16 gAmh[(size_t)FP * NN];
__device__ __nv_bfloat16 gAml[(size_t)FP * NN];
// H planes (Y role only): r, s, m
__device__ __nv_bfloat16 gHrh[(size_t)BB * NN * NN];
__device__ __nv_bfloat16 gHrl[(size_t)BB * NN * NN];
__device__ __nv_bfloat16 gHsh[(size_t)BB * NN * NN];
__device__ __nv_bfloat16 gHsl[(size_t)BB * NN * NN];
__device__ __nv_bfloat16 gHmh[(size_t)BB * NN * NN];
__device__ __nv_bfloat16 gHml[(size_t)BB * NN * NN];
// T planes (X role only): s, r, i
__device__ __nv_bfloat16 gTsh[(size_t)BB * FP * NN];
__device__ __nv_bfloat16 gTsl[(size_t)BB * FP * NN];
__device__ __nv_bfloat16 gTrh[(size_t)BB * FP * NN];
__device__ __nv_bfloat16 gTrl[(size_t)BB * FP * NN];
__device__ __nv_bfloat16 gTih[(size_t)BB * FP * NN];
__device__ __nv_bfloat16 gTil[(size_t)BB * FP * NN];

// ---------------- helpers ----------------
__device__ __forceinline__ uint32_t smem_u32(const void* p) {
    uint32_t a;
    asm("{ .reg .u64 t; cvta.to.shared.u64 t, %1; cvt.u32.u64 %0, t; }" : "=r"(a) : "l"(p));
    return a;
}
#define SWZ64(off) ((off) ^ (((off) >> 3) & 0x30))

#define CPA16(dst, src) \
    asm volatile("cp.async.cg.shared.global [%0], [%1], 16;" :: "r"(dst), "l"(src))
#define CPA_COMMIT() asm volatile("cp.async.commit_group;" ::: "memory")
#define CPA_WAIT(n)  asm volatile("cp.async.wait_group %0;" :: "n"(n) : "memory")

__device__ __forceinline__ void ldsm4(uint32_t* r, uint32_t addr) {
    asm volatile("ldmatrix.sync.aligned.m8n8.x4.shared.b16 {%0,%1,%2,%3}, [%4];"
        : "=r"(r[0]), "=r"(r[1]), "=r"(r[2]), "=r"(r[3]) : "r"(addr));
}
__device__ __forceinline__ void mma16816(float* c, const uint32_t* a,
                                         uint32_t b0, uint32_t b1) {
    asm volatile(
        "mma.sync.aligned.m16n8k16.row.col.f32.bf16.bf16.f32 "
        "{%0,%1,%2,%3}, {%4,%5,%6,%7}, {%8,%9}, {%0,%1,%2,%3};"
        : "+f"(c[0]), "+f"(c[1]), "+f"(c[2]), "+f"(c[3])
        : "r"(a[0]), "r"(a[1]), "r"(a[2]), "r"(a[3]), "r"(b0), "r"(b1));
}
__device__ __forceinline__ void split2(float v, __nv_bfloat16& h, __nv_bfloat16& l) {
    h = __float2bfloat16_rn(v);
    l = __float2bfloat16_rn(v - __bfloat162float(h));
}

// ---------------------------------------------------------------------------
// Kernel 1: amplitudes -> 8 bf16 split planes (r, i, s, m; rows >= FF zeroed)
// ---------------------------------------------------------------------------
__global__ void amp_kernel(const float* __restrict__ U_re,
                           const float* __restrict__ U_im) {
    __shared__ float sUre[MMODES * MMODES];
    __shared__ float sUim[MMODES * MMODES];
    for (int t = threadIdx.x; t < MMODES * MMODES; t += blockDim.x) {
        sUre[t] = U_re[t];
        sUim[t] = U_im[t];
    }
    __syncthreads();

    int f = blockIdx.x;
    if (f >= FF) {
        __nv_bfloat16 z = __float2bfloat16(0.f);
        for (int i = threadIdx.x; i < NN; i += blockDim.x) {
            size_t o = (size_t)f * NN + i;
            gArh[o] = z; gArl[o] = z; gAih[o] = z; gAil[o] = z;
            gAsh[o] = z; gAsl[o] = z; gAmh[o] = z; gAml[o] = z;
        }
        return;
    }
    int j = 0, rem = f;
    while (rem >= (MMODES - j)) { rem -= (MMODES - j); j++; }
    int k = j + rem;
    float scale = (j == k) ? 0.70710678118654752f : 1.0f;

    for (int i = threadIdx.x; i < NN; i += blockDim.x) {
        int x = i >> 5, y = i & 31;
        float are = sUre[j * MMODES + x],       aim = sUim[j * MMODES + x];
        float bre = sUre[k * MMODES + DD + y],  bim = sUim[k * MMODES + DD + y];
        float cre = sUre[k * MMODES + x],       cim = sUim[k * MMODES + x];
        float dre = sUre[j * MMODES + DD + y],  dim_ = sUim[j * MMODES + DD + y];
        float re = (are * bre - aim * bim + cre * dre - cim * dim_) * scale;
        float im = (are * bim + aim * bre + cre * dim_ + cim * dre) * scale;
        size_t o = (size_t)f * NN + i;
        __nv_bfloat16 h, l;
        split2(re, h, l);       gArh[o] = h; gArl[o] = l;
        split2(im, h, l);       gAih[o] = h; gAil[o] = l;
        split2(re + im, h, l);  gAsh[o] = h; gAsl[o] = l;
        split2(re - im, h, l);  gAmh[o] = h; gAml[o] = l;
    }
}

// ---------------------------------------------------------------------------
// Kernel 2: Hermitian H build -> 6 bf16 split planes (r, s=r+i, m=r-i)
// ---------------------------------------------------------------------------
#define HT 32
__global__ __launch_bounds__(256) void herm_kernel(const float* __restrict__ rho_re,
                                                   const float* __restrict__ rho_im) {
    int p = blockIdx.x, ti = 0;
    while (p >= (HT - ti)) { p -= (HT - ti); ti++; }
    int tj = ti + p;
    int b = blockIdx.y;

    __shared__ float sRe[HT][HT + 1];
    __shared__ float sIm[HT][HT + 1];

    size_t base = (size_t)b * NN * NN;
    int r0 = ti * HT, c0 = tj * HT;
    int t = threadIdx.x;

    #pragma unroll
    for (int it = 0; it < 4; it++) {
        int slot = it * 256 + t;
        int r = slot >> 5, c = slot & 31;
        size_t g = base + (size_t)(r0 + r) * NN + c0 + c;
        sRe[r][c] = rho_re[g];
        sIm[r][c] = rho_im[g];
    }
    __syncthreads();

    #pragma unroll
    for (int it = 0; it < 4; it++) {
        int slot = it * 256 + t;
        int r = slot >> 5, c = slot & 31;
        float vre, vim;
        if (ti < tj) { vre = sRe[r][c]; vim = sIm[r][c]; }
        else if (r < c) { vre = sRe[r][c]; vim = sIm[r][c]; }
        else if (r > c) { vre = sRe[c][r]; vim = -sIm[c][r]; }
        else { vre = sRe[r][c]; vim = 0.0f; }
        size_t o = base + (size_t)(r0 + r) * NN + c0 + c;
        __nv_bfloat16 h, l;
        split2(vre, h, l);        gHrh[o] = h; gHrl[o] = l;
        split2(vre + vim, h, l);  gHsh[o] = h; gHsl[o] = l;
        split2(vre - vim, h, l);  gHmh[o] = h; gHml[o] = l;
    }
    if (ti < tj) {
        #pragma unroll
        for (int it = 0; it < 4; it++) {
            int slot = it * 256 + t;
            int r = slot >> 5, c = slot & 31;
            float vre = sRe[c][r], vim = -sIm[c][r];
            size_t o = base + (size_t)(c0 + r) * NN + r0 + c;
            __nv_bfloat16 h, l;
            split2(vre, h, l);        gHrh[o] = h; gHrl[o] = l;
            split2(vre + vim, h, l);  gHsh[o] = h; gHsl[o] = l;
            split2(vre - vim, h, l);  gHmh[o] = h; gHml[o] = l;
        }
    }
}

// ---------------------------------------------------------------------------
// Unified Karatsuba split-bf16 complex GEMM:  C = X * conj(Y)^T
//   k1 = (Xr+Xi)*Yr ; K2' = Xr*(Yr+Yi) ; k3 = Xi*(Yr-Yi)
//   re = k1 - k3 ; im = k1 - K2'
// X plane order in smem: s_h s_l r_h r_l i_h i_l
// Y plane order in smem: r_h r_l s_h s_l m_h m_l
//   mode 0: X = Amp, Y = H rows   -> bf16-split T (planes s,r,i)
//   mode 1: X = T,   Y = Amp      -> float2 out (+ conj mirror)
// ---------------------------------------------------------------------------
__global__ __launch_bounds__(256, 1) void gemm_kernel(int mode, float2* __restrict__ out) {
    extern __shared__ char dsm[];
    uint32_t sbraw = smem_u32(dsm);
    uint32_t sb = (sbraw + 1023u) & ~1023u;
    char* smem = dsm + (sb - sbraw);

    const int t = threadIdx.x;
    const int lane = t & 31;
    const int wid = t >> 5;
    const int wm = wid & 3;       // 4 warps along M (32 rows each)
    const int wn = wid >> 2;      // 2 warps along N (32 cols each)

    int b, f0, n0, tf = 0, tg = 0;
    const __nv_bfloat16 *Xp[6], *Yp[6];
    if (mode == 0) {
        b = blockIdx.z; f0 = blockIdx.y * BM; n0 = blockIdx.x * BN;
        size_t ab = (size_t)f0 * NN;
        Xp[0] = gAsh + ab; Xp[1] = gAsl + ab; Xp[2] = gArh + ab;
        Xp[3] = gArl + ab; Xp[4] = gAih + ab; Xp[5] = gAil + ab;
        size_t bbo = ((size_t)b * NN + n0) * NN;
        Yp[0] = gHrh + bbo; Yp[1] = gHrl + bbo; Yp[2] = gHsh + bbo;
        Yp[3] = gHsl + bbo; Yp[4] = gHmh + bbo; Yp[5] = gHml + bbo;
    } else {
        b = blockIdx.y;
        int p = blockIdx.x;
        while (p >= (NCOLT - 2 * tf)) { p -= (NCOLT - 2 * tf); tf++; }
        tg = 2 * tf + p;
        f0 = tf * BM; n0 = tg * BN;
        size_t ab = ((size_t)b * FP + f0) * NN;
        Xp[0] = gTsh + ab; Xp[1] = gTsl + ab; Xp[2] = gTrh + ab;
        Xp[3] = gTrl + ab; Xp[4] = gTih + ab; Xp[5] = gTil + ab;
        size_t bbo = (size_t)n0 * NN;
        Yp[0] = gArh + bbo; Yp[1] = gArl + bbo; Yp[2] = gAsh + bbo;
        Yp[3] = gAsl + bbo; Yp[4] = gAmh + bbo; Yp[5] = gAml + bbo;
    }

    // ---- prefetch: 18 cp.async per thread per stage ----
    auto prefetch = [&](uint32_t stOff, int k0) {
        #pragma unroll
        for (int it = 0; it < 12; it++) {            // X: 6*128*4 = 3072 chunks
            int slot = it * 256 + t;
            int v = slot >> 9;
            int rem = slot & 511;
            int row = rem >> 2, c16 = rem & 3;
            uint32_t dst = sb + stOff + v * XPL + SWZ64(row * 64 + c16 * 16);
            const char* src = (const char*)(Xp[v] + (size_t)row * NN + k0) + c16 * 16;
            CPA16(dst, src);
        }
        #pragma unroll
        for (int it = 0; it < 6; it++) {             // Y: 6*64*4 = 1536 chunks
            int slot = it * 256 + t;
            int v = slot >> 8;
            int rem = slot & 255;
            int row = rem >> 2, c16 = rem & 3;
            uint32_t dst = sb + stOff + YOFF + v * YPL + SWZ64(row * 64 + c16 * 16);
            const char* src = (const char*)(Yp[v] + (size_t)row * NN + k0) + c16 * 16;
            CPA16(dst, src);
        }
    };

    float acc1[2][4][4], acc2[2][4][4], acc3[2][4][4];
    #pragma unroll
    for (int mt = 0; mt < 2; mt++)
        #pragma unroll
        for (int nt = 0; nt < 4; nt++)
            #pragma unroll
            for (int q = 0; q < 4; q++) {
                acc1[mt][nt][q] = 0.f; acc2[mt][nt][q] = 0.f; acc3[mt][nt][q] = 0.f;
            }

    // per-lane ldmatrix addressing (64B rows, SW64)
    const int lrow = lane & 15;
    const uint32_t c16base = (uint32_t)(lane >> 4);   // 0 or 1
    uint32_t aOff[2], aXm[2], bOff[2], bXm[2];
    #pragma unroll
    for (int mt = 0; mt < 2; mt++) {
        int row = wm * 32 + mt * 16 + lrow;
        aOff[mt] = row * 64;
        aXm[mt] = (row >> 1) & 3;
    }
    #pragma unroll
    for (int pr = 0; pr < 2; pr++) {
        int row = wn * 32 + pr * 16 + lrow;
        bOff[pr] = row * 64;
        bXm[pr] = (row >> 1) & 3;
    }

    // one Karatsuba product pass: X planes (xp, xp+1), Y planes (yp, yp+1)
    auto pass = [&](uint32_t stBase, uint32_t c16, int xp, int yp,
                    float (&acc)[2][4][4]) {
        uint32_t Xh[2][4], Xl[2][4];
        #pragma unroll
        for (int mt = 0; mt < 2; mt++) {
            ldsm4(Xh[mt], stBase + xp * XPL + aOff[mt] + ((c16 ^ aXm[mt]) << 4));
            ldsm4(Xl[mt], stBase + (xp + 1) * XPL + aOff[mt] + ((c16 ^ aXm[mt]) << 4));
        }
        uint32_t Yh[2][4], Yl[2][4];
        #pragma unroll
        for (int pr = 0; pr < 2; pr++) {
            ldsm4(Yh[pr], stBase + YOFF + yp * YPL + bOff[pr] + ((c16 ^ bXm[pr]) << 4));
            ldsm4(Yl[pr], stBase + YOFF + (yp + 1) * YPL + bOff[pr] + ((c16 ^ bXm[pr]) << 4));
        }
        #pragma unroll
        for (int mt = 0; mt < 2; mt++)
            #pragma unroll
            for (int nt = 0; nt < 4; nt++) {
                const int pr = nt >> 1, hh = nt & 1;
                float* c = acc[mt][nt];
                mma16816(c, Xh[mt], Yh[pr][hh], Yh[pr][hh + 2]);
                mma16816(c, Xh[mt], Yl[pr][hh], Yl[pr][hh + 2]);
                mma16816(c, Xl[mt], Yh[pr][hh], Yh[pr][hh + 2]);
            }
    };

    prefetch(0, 0);
    CPA_COMMIT();
    prefetch(STAGE_BYTES, BKC);
    CPA_COMMIT();

    for (int c = 0; c < NCH; c++) {
        CPA_WAIT(1);
        __syncthreads();
        if (c + 2 < NCH)
            prefetch(((c + 2) % NSTAGE) * STAGE_BYTES, (c + 2) * BKC);
        CPA_COMMIT();

        const uint32_t stBase = sb + (c % NSTAGE) * STAGE_BYTES;
        #pragma unroll
        for (int ks = 0; ks < KS; ks++) {
            const uint32_t c16 = (uint32_t)(ks * 2) + c16base;
            pass(stBase, c16, 0, 0, acc1);   // k1 = (Xr+Xi)*Yr
            pass(stBase, c16, 2, 2, acc2);   // K2' = Xr*(Yr+Yi)
            pass(stBase, c16, 4, 4, acc3);   // k3 = Xi*(Yr-Yi)
        }
    }
    __syncthreads();   // stage smem about to be reused for epilogue staging

    // ---- epilogue: combine + stage in smem + coalesced writeback ----
    const int erow0 = wm * 32 + (lane >> 2);
    const int ecol0 = wn * 32 + (lane & 3) * 2;

    if (mode == 0) {
        #pragma unroll
        for (int mt = 0; mt < 2; mt++)
            #pragma unroll
            for (int nt = 0; nt < 4; nt++) {
                int col = ecol0 + nt * 8;
                #pragma unroll
                for (int hlf = 0; hlf < 2; hlf++) {
                    int row = erow0 + mt * 16 + hlf * 8;
                    #pragma unroll
                    for (int q = 0; q < 2; q++) {
                        float k1 = acc1[mt][nt][hlf * 2 + q];
                        float re = k1 - acc3[mt][nt][hlf * 2 + q];
                        float im = k1 - acc2[mt][nt][hlf * 2 + q];
                        int cc = col + q;
                        __nv_bfloat16 h, l;
                        split2(re + im, h, l);
                        *(__nv_bfloat16*)(smem + 0 * PLANE_T + row * PITCH_T + cc * 2) = h;
                        *(__nv_bfloat16*)(smem + 1 * PLANE_T + row * PITCH_T + cc * 2) = l;
                        split2(re, h, l);
                        *(__nv_bfloat16*)(smem + 2 * PLANE_T + row * PITCH_T + cc * 2) = h;
                        *(__nv_bfloat16*)(smem + 3 * PLANE_T + row * PITCH_T + cc * 2) = l;
                        split2(im, h, l);
                        *(__nv_bfloat16*)(smem + 4 * PLANE_T + row * PITCH_T + cc * 2) = h;
                        *(__nv_bfloat16*)(smem + 5 * PLANE_T + row * PITCH_T + cc * 2) = l;
                    }
                }
            }
        __syncthreads();

        __nv_bfloat16* Td[6];
        size_t tb0 = ((size_t)b * FP + f0) * NN + n0;
        Td[0] = gTsh + tb0; Td[1] = gTsl + tb0; Td[2] = gTrh + tb0;
        Td[3] = gTrl + tb0; Td[4] = gTih + tb0; Td[5] = gTil + tb0;
        #pragma unroll
        for (int v = 0; v < 6; v++) {
            #pragma unroll
            for (int it = 0; it < 8; it++) {
                int slot = it * 256 + t;
                int row = slot >> 4, c8 = slot & 15;
                uint2 val = *(uint2*)(smem + v * PLANE_T + row * PITCH_T + c8 * 8);
                *(uint2*)(Td[v] + (size_t)row * NN + c8 * 4) = val;
            }
        }
    } else {
        #pragma unroll
        for (int mt = 0; mt < 2; mt++)
            #pragma unroll
            for (int nt = 0; nt < 4; nt++) {
                int col = ecol0 + nt * 8;
                #pragma unroll
                for (int hlf = 0; hlf < 2; hlf++) {
                    int row = erow0 + mt * 16 + hlf * 8;
                    float k1a = acc1[mt][nt][hlf * 2 + 0];
                    float k1b = acc1[mt][nt][hlf * 2 + 1];
                    float4 v4;
                    v4.x = k1a - acc3[mt][nt][hlf * 2 + 0];
                    v4.y = k1a - acc2[mt][nt][hlf * 2 + 0];
                    v4.z = k1b - acc3[mt][nt][hlf * 2 + 1];
                    v4.w = k1b - acc2[mt][nt][hlf * 2 + 1];
                    *(float4*)(smem + row * PITCH_O + col * 8) = v4;
                }
            }
        __syncthreads();

        const size_t obase = (size_t)b * FF;
        #pragma unroll 4
        for (int it = 0; it < 32; it++) {
            int slot = it * 256 + t;
            int row = slot >> 6, cc = slot & 63;
            int fr = f0 + row, gc = n0 + cc;
            if (fr < FF && gc < FF) {
                float2 v = *(float2*)(smem + row * PITCH_O + cc * 8);
                out[(obase + fr) * FF + gc] = v;
            }
        }
        if (tg >= 2 * tf + 2) {   // off-band: mirror conj-transpose
            #pragma unroll 4
            for (int it = 0; it < 32; it++) {
                int slot = it * 256 + t;
                int g = slot >> 7, ff = slot & 127;
                int gr = n0 + g, fc = f0 + ff;
                if (gr < FF && fc < FF) {
                    float2 v = *(float2*)(smem + ff * PITCH_O + g * 8);
                    out[(obase + gr) * FF + fc] = make_float2(v.x, -v.y);
                }
            }
        }
    }
}

// ---------------------------------------------------------------------------
extern "C" void kernel_launch(void* const* d_in, const int* in_sizes, int n_in,
                              void* d_out, int out_size) {
    const float* rho_re = (const float*)d_in[0];
    const float* rho_im = (const float*)d_in[1];
    const float* U_re   = (const float*)d_in[2];
    const float* U_im   = (const float*)d_in[3];
    float2* out = (float2*)d_out;

    static int attr_set = 0;
    if (!attr_set) {
        cudaFuncSetAttribute(gemm_kernel, cudaFuncAttributeMaxDynamicSharedMemorySize, SMEM_DYN);
        attr_set = 1;
    }

    amp_kernel<<<FP, 256>>>(U_re, U_im);

    dim3 hg(HT * (HT + 1) / 2, BB);
    herm_kernel<<<hg, 256>>>(rho_re, rho_im);

    dim3 g1(NN / BN, NROWT, BB);
    gemm_kernel<<<g1, 256, SMEM_DYN>>>(0, nullptr);

    dim3 g2(NPAIR2, BB);
    gemm_kernel<<<g2, 256, SMEM_DYN>>>(1, out);
}